// round 9
// baseline (speedup 1.0000x reference)
#include <cuda_runtime.h>
#include <cstdint>

// OcrEmbedding: out[b,t,:] = sum_{s=0..3, id!=0} table[id[b,t,s], :]
// B=32, T=512, S=4, D=256, V=50000.
// d_in[0] = subtoken_ids (int32, B*T*S), d_in[1] = table (float32, V*D)
// Output: float32, B*T*D.
//
// Champion shape (R1: 64 threads per token row, 1 float4/thread) at the
// chip LTS ceiling (~7.9 TB/s for 84MB of L2 traffic). Refinements:
//  - 128-thread CTAs (8192 blocks): finer scheduling granularity, less
//    wave-quantization tail than 256-thread/4096.
//  - branch-free masking for id==0 (multiply by 0/1) - removes BSSY/BSYNC.
//  - __stcs output stores (evict-first, never re-read).

#define BT   (32 * 512)   // 16384 token rows
#define D4   64           // float4 chunks per 256-float row

__global__ __launch_bounds__(128) void ocr_embed_kernel(
    const int* __restrict__ ids,          // [BT*4]
    const float* __restrict__ table,      // [V*256]
    float4* __restrict__ out)             // [BT, D4]
{
    const int gid = blockIdx.x * 128 + threadIdx.x;
    const int row = gid >> 6;             // token index
    const int q   = gid & 63;             // float4 chunk within D

    const int4 id = __ldg((const int4*)(ids + row * 4));

    // Branch-free: always load (ids are valid row indices incl. 0), mask the
    // padding row's contribution with a 0/1 multiplier.
    const float m0 = (id.x != 0) ? 1.0f : 0.0f;
    const float m1 = (id.y != 0) ? 1.0f : 0.0f;
    const float m2 = (id.z != 0) ? 1.0f : 0.0f;
    const float m3 = (id.w != 0) ? 1.0f : 0.0f;

    const float4 v0 = __ldcs((const float4*)(table + (size_t)id.x * 256) + q);
    const float4 v1 = __ldcs((const float4*)(table + (size_t)id.y * 256) + q);
    const float4 v2 = __ldcs((const float4*)(table + (size_t)id.z * 256) + q);
    const float4 v3 = __ldcs((const float4*)(table + (size_t)id.w * 256) + q);

    float4 s;
    s.x = fmaf(m0, v0.x, 0.f); s.y = fmaf(m0, v0.y, 0.f);
    s.z = fmaf(m0, v0.z, 0.f); s.w = fmaf(m0, v0.w, 0.f);
    s.x = fmaf(m1, v1.x, s.x); s.y = fmaf(m1, v1.y, s.y);
    s.z = fmaf(m1, v1.z, s.z); s.w = fmaf(m1, v1.w, s.w);
    s.x = fmaf(m2, v2.x, s.x); s.y = fmaf(m2, v2.y, s.y);
    s.z = fmaf(m2, v2.z, s.z); s.w = fmaf(m2, v2.w, s.w);
    s.x = fmaf(m3, v3.x, s.x); s.y = fmaf(m3, v3.y, s.y);
    s.z = fmaf(m3, v3.z, s.z); s.w = fmaf(m3, v3.w, s.w);

    __stcs(&out[(size_t)row * D4 + q], s);
}

extern "C" void kernel_launch(void* const* d_in, const int* in_sizes, int n_in,
                              void* d_out, int out_size)
{
    const int*   ids   = (const int*)d_in[0];
    const float* table = (const float*)d_in[1];
    float4*      out   = (float4*)d_out;

    const int total   = BT * 64;          // one thread per float4 chunk
    const int threads = 128;
    const int blocks  = total / threads;  // 8192

    ocr_embed_kernel<<<blocks, threads>>>(ids, table, out);
}